// round 1
// baseline (speedup 1.0000x reference)
#include <cuda_runtime.h>

// Problem constants
// x:     (16, 256, 64, 64)  -> [b][c][n], n = 4096
// w_qkv: (768, 256)
// w_out: (256, 256)
// b_out: (256,)
// out:   (16, 256, 64, 64)

static const long long QKV_ELEMS = 16LL * 768 * 4096;

__device__ float g_qkv[16LL * 768 * 4096];   // qkv intermediate (q softmaxed in place)
__device__ float g_ctx[16 * 4 * 64 * 64];    // context per (b, h)
__device__ float g_w2[16 * 256 * 256];       // fused (w_out x ctx) per batch

// ---------------------------------------------------------------------------
// Tiled SGEMM: C[b] = A[b] (M x K, row-major lda) @ X[b] (K x 4096) [+ bias]
// BM=BN=128, BK=8, 256 threads, 8x8 per-thread micro-tile.
// M, K multiples of 128/8; N fixed 4096.
// ---------------------------------------------------------------------------
__global__ __launch_bounds__(256) void sgemm_kernel(
    const float* __restrict__ A, long long strideA, int lda,
    const float* __restrict__ Bm, long long strideB,
    float* __restrict__ Cm, long long strideC,
    int Mdim, int Kdim, const float* __restrict__ bias)
{
    const int NN = 4096;
    const int n0 = blockIdx.x * 128;
    const int m0 = blockIdx.y * 128;
    const int bz = blockIdx.z;
    A  += (long long)bz * strideA;
    Bm += (long long)bz * strideB;
    Cm += (long long)bz * strideC;

    __shared__ float As[8][128];
    __shared__ float Bs[8][128];

    const int tid  = threadIdx.x;
    const int ty   = tid >> 4;          // 0..15
    const int tx   = tid & 15;          // 0..15
    const int arow = tid >> 1;          // 0..127
    const int ac4  = (tid & 1) * 4;     // 0 or 4
    const int brow = tid >> 5;          // 0..7
    const int bc4  = (tid & 31) * 4;    // 0..124

    float acc[8][8];
    #pragma unroll
    for (int i = 0; i < 8; i++)
        #pragma unroll
        for (int j = 0; j < 8; j++) acc[i][j] = 0.f;

    for (int k0 = 0; k0 < Kdim; k0 += 8) {
        float4 av = *(const float4*)(A  + (long long)(m0 + arow) * lda + k0 + ac4);
        float4 bv = *(const float4*)(Bm + (long long)(k0 + brow) * NN + n0 + bc4);
        __syncthreads();
        As[ac4 + 0][arow] = av.x;
        As[ac4 + 1][arow] = av.y;
        As[ac4 + 2][arow] = av.z;
        As[ac4 + 3][arow] = av.w;
        *(float4*)&Bs[brow][bc4] = bv;
        __syncthreads();
        #pragma unroll
        for (int k = 0; k < 8; k++) {
            float a[8], b[8];
            *(float4*)(a    ) = *(const float4*)&As[k][ty * 8];
            *(float4*)(a + 4) = *(const float4*)&As[k][ty * 8 + 4];
            *(float4*)(b    ) = *(const float4*)&Bs[k][tx * 8];
            *(float4*)(b + 4) = *(const float4*)&Bs[k][tx * 8 + 4];
            #pragma unroll
            for (int i = 0; i < 8; i++)
                #pragma unroll
                for (int j = 0; j < 8; j++)
                    acc[i][j] = fmaf(a[i], b[j], acc[i][j]);
        }
    }

    #pragma unroll
    for (int i = 0; i < 8; i++) {
        const int m = m0 + ty * 8 + i;
        const float bb = bias ? bias[m] : 0.f;
        float4 o0 = make_float4(acc[i][0] + bb, acc[i][1] + bb, acc[i][2] + bb, acc[i][3] + bb);
        float4 o1 = make_float4(acc[i][4] + bb, acc[i][5] + bb, acc[i][6] + bb, acc[i][7] + bb);
        *(float4*)(Cm + (long long)m * NN + n0 + tx * 8)     = o0;
        *(float4*)(Cm + (long long)m * NN + n0 + tx * 8 + 4) = o1;
    }
}

// ---------------------------------------------------------------------------
// q softmax over d (64, strided), times SCALE=1/8.  In place on qkv rows 0..255.
// One thread per (b,h,n) column: 64 values live in registers.
// ---------------------------------------------------------------------------
__global__ __launch_bounds__(256) void softmax_q_kernel(float* __restrict__ qkv)
{
    const int n = blockIdx.x * 256 + threadIdx.x;
    const int h = blockIdx.y;
    const int b = blockIdx.z;
    float* base = qkv + ((long long)b * 768 + h * 64) * 4096 + n;

    float v[64];
    float m = -1e30f;
    #pragma unroll
    for (int d = 0; d < 64; d++) {
        v[d] = base[(long long)d * 4096];
        m = fmaxf(m, v[d]);
    }
    float s = 0.f;
    #pragma unroll
    for (int d = 0; d < 64; d++) {
        v[d] = expf(v[d] - m);
        s += v[d];
    }
    const float r = 0.125f / s;   // SCALE = 64^-0.5
    #pragma unroll
    for (int d = 0; d < 64; d++)
        base[(long long)d * 4096] = v[d] * r;
}

// ---------------------------------------------------------------------------
// k softmax over n (4096, contiguous). One block per (b, h*64+d) row.
// ---------------------------------------------------------------------------
__global__ __launch_bounds__(256) void softmax_k_kernel(float* __restrict__ qkv)
{
    const int r   = blockIdx.x;       // 0..4095
    const int b   = r >> 8;
    const int rem = r & 255;
    float* base = qkv + ((long long)b * 768 + 256 + rem) * 4096;
    const int tid = threadIdx.x;

    float v[16];
    float m = -1e30f;
    #pragma unroll
    for (int i = 0; i < 16; i++) {
        v[i] = base[tid + i * 256];
        m = fmaxf(m, v[i]);
    }
    __shared__ float red[8];
    #pragma unroll
    for (int o = 16; o; o >>= 1) m = fmaxf(m, __shfl_xor_sync(0xffffffffu, m, o));
    if ((tid & 31) == 0) red[tid >> 5] = m;
    __syncthreads();
    if (tid == 0) {
        float t = red[0];
        for (int i = 1; i < 8; i++) t = fmaxf(t, red[i]);
        red[0] = t;
    }
    __syncthreads();
    m = red[0];
    __syncthreads();

    float s = 0.f;
    #pragma unroll
    for (int i = 0; i < 16; i++) {
        v[i] = expf(v[i] - m);
        s += v[i];
    }
    #pragma unroll
    for (int o = 16; o; o >>= 1) s += __shfl_xor_sync(0xffffffffu, s, o);
    if ((tid & 31) == 0) red[tid >> 5] = s;
    __syncthreads();
    if (tid == 0) {
        float t = 0.f;
        for (int i = 0; i < 8; i++) t += red[i];
        red[0] = t;
    }
    __syncthreads();
    const float inv = 1.f / red[0];
    #pragma unroll
    for (int i = 0; i < 16; i++)
        base[tid + i * 256] = v[i] * inv;
}

// ---------------------------------------------------------------------------
// context[b,h,d,e] = sum_n k[b,h,d,n] * v[b,h,e,n]
// One block per (b,h); 256 threads, 4x4 per-thread tile, n chunked by 32.
// ---------------------------------------------------------------------------
__global__ __launch_bounds__(256) void context_kernel(
    const float* __restrict__ qkv, float* __restrict__ ctx)
{
    const int h = blockIdx.x;
    const int b = blockIdx.y;
    const float* Kp = qkv + ((long long)b * 768 + 256 + h * 64) * 4096;
    const float* Vp = qkv + ((long long)b * 768 + 512 + h * 64) * 4096;

    __shared__ float ks[64][33];
    __shared__ float vs[64][33];

    const int tid = threadIdx.x;
    const int ty = tid >> 4, tx = tid & 15;
    float acc[4][4];
    #pragma unroll
    for (int i = 0; i < 4; i++)
        #pragma unroll
        for (int j = 0; j < 4; j++) acc[i][j] = 0.f;

    for (int n0 = 0; n0 < 4096; n0 += 32) {
        __syncthreads();
        #pragma unroll
        for (int i = 0; i < 8; i++) {
            const int idx = tid + i * 256;
            const int d = idx >> 5, j = idx & 31;
            ks[d][j] = Kp[(long long)d * 4096 + n0 + j];
            vs[d][j] = Vp[(long long)d * 4096 + n0 + j];
        }
        __syncthreads();
        #pragma unroll
        for (int j = 0; j < 32; j++) {
            float a[4], bb[4];
            #pragma unroll
            for (int i = 0; i < 4; i++) a[i]  = ks[ty * 4 + i][j];
            #pragma unroll
            for (int i = 0; i < 4; i++) bb[i] = vs[tx * 4 + i][j];
            #pragma unroll
            for (int i = 0; i < 4; i++)
                #pragma unroll
                for (int e = 0; e < 4; e++)
                    acc[i][e] = fmaf(a[i], bb[e], acc[i][e]);
        }
    }
    float* cbase = ctx + (long long)(b * 4 + h) * 64 * 64;
    #pragma unroll
    for (int i = 0; i < 4; i++)
        #pragma unroll
        for (int e = 0; e < 4; e++)
            cbase[(ty * 4 + i) * 64 + tx * 4 + e] = acc[i][e];
}

// ---------------------------------------------------------------------------
// W2[b][o, h*64+d] = sum_e w_out[o, h*64+e] * ctx[b,h,d,e]
// One block per (b,h); o chunked by 64 through smem.
// ---------------------------------------------------------------------------
__global__ __launch_bounds__(256) void w2_kernel(
    const float* __restrict__ ctx, const float* __restrict__ w_out,
    float* __restrict__ w2)
{
    const int h = blockIdx.x;
    const int b = blockIdx.y;
    __shared__ float cs[64][65];
    __shared__ float ws[64][65];
    const int tid = threadIdx.x;

    const float* cbase = ctx + (long long)(b * 4 + h) * 4096;
    #pragma unroll
    for (int i = 0; i < 16; i++) {
        const int idx = tid + i * 256;
        cs[idx >> 6][idx & 63] = cbase[idx];
    }
    float* w2base = w2 + (long long)b * 65536;   // [o][m], m = h*64+d

    for (int oc = 0; oc < 4; oc++) {
        __syncthreads();
        #pragma unroll
        for (int i = 0; i < 16; i++) {
            const int idx = tid + i * 256;
            const int ol = idx >> 6, e = idx & 63;
            ws[ol][e] = w_out[(oc * 64 + ol) * 256 + h * 64 + e];
        }
        __syncthreads();
        const int ol    = tid & 63;
        const int dbase = (tid >> 6) * 16;
        for (int dd = 0; dd < 16; dd++) {
            const int d = dbase + dd;
            float s = 0.f;
            #pragma unroll
            for (int e = 0; e < 64; e++)
                s = fmaf(ws[ol][e], cs[d][e], s);
            w2base[(oc * 64 + ol) * 256 + h * 64 + d] = s;
        }
    }
}

// ---------------------------------------------------------------------------
extern "C" void kernel_launch(void* const* d_in, const int* in_sizes, int n_in,
                              void* d_out, int out_size)
{
    // Defensive input mapping by element count (all four are distinct).
    const float* x = nullptr, *w_qkv = nullptr, *w_out = nullptr, *b_out = nullptr;
    for (int i = 0; i < n_in; i++) {
        switch (in_sizes[i]) {
            case 16 * 256 * 4096: x     = (const float*)d_in[i]; break;
            case 768 * 256:       w_qkv = (const float*)d_in[i]; break;
            case 256 * 256:       w_out = (const float*)d_in[i]; break;
            case 256:             b_out = (const float*)d_in[i]; break;
        }
    }
    float* out = (float*)d_out;

    float *qkv, *ctx, *w2;
    cudaGetSymbolAddress((void**)&qkv, g_qkv);
    cudaGetSymbolAddress((void**)&ctx, g_ctx);
    cudaGetSymbolAddress((void**)&w2,  g_w2);

    // 1) qkv[b] = w_qkv @ x[b]           (768 x 4096, K=256) x 16
    sgemm_kernel<<<dim3(32, 6, 16), 256>>>(
        w_qkv, 0LL, 256, x, 256LL * 4096, qkv, 768LL * 4096, 768, 256, nullptr);

    // 2) q softmax over d (in place, rows 0..255 of each batch), * SCALE
    softmax_q_kernel<<<dim3(16, 4, 16), 256>>>(qkv);

    // 3) k softmax over n (in place, rows 256..511 of each batch)
    softmax_k_kernel<<<4096, 256>>>(qkv);

    // 4) context[b,h] = k @ v^T   (64x64, K=4096)
    context_kernel<<<dim3(4, 16), 256>>>(qkv, ctx);

    // 5) W2[b] = w_out-slice @ ctx^T fusion (collapses out-projection + PV GEMM)
    w2_kernel<<<dim3(4, 16), 256>>>(ctx, w_out, w2);

    // 6) out[b] = W2[b] @ q_softmaxed[b] + b_out   (256 x 4096, K=256) x 16
    sgemm_kernel<<<dim3(32, 2, 16), 256>>>(
        w2, 256LL * 256, 256, qkv, 768LL * 4096, out, 256LL * 4096, 256, 256, b_out);
}

// round 2
// speedup vs baseline: 2.3295x; 2.3295x over previous
#include <cuda_runtime.h>

// Shapes: x (16,256,4096), w_qkv (768,256), w_out (256,256), b_out (256)
__device__ float g_qkv[16LL * 768 * 4096];   // qkv intermediate (softmaxed in place)
__device__ float g_ctx[16 * 4 * 64 * 64];    // context per (b, h)
__device__ float g_w2[16 * 256 * 256];       // fused (w_out x ctx) per batch

__device__ __forceinline__ unsigned f2tf32(float f) {
    unsigned u; asm("cvt.rna.tf32.f32 %0, %1;" : "=r"(u) : "f"(f)); return u;
}

__device__ __forceinline__ void mma8(float* c, const unsigned* a, const unsigned* b) {
    asm volatile(
        "mma.sync.aligned.m16n8k8.row.col.f32.tf32.tf32.f32 "
        "{%0,%1,%2,%3},{%4,%5,%6,%7},{%8,%9},{%0,%1,%2,%3};"
        : "+f"(c[0]), "+f"(c[1]), "+f"(c[2]), "+f"(c[3])
        : "r"(a[0]), "r"(a[1]), "r"(a[2]), "r"(a[3]), "r"(b[0]), "r"(b[1]));
}

#define SA 136

// ---------------------------------------------------------------------------
// TF32 tensor-core GEMM: C[b] = A[b](M x K, lda) @ B[b](K x 4096) [+bias]
// 128x128 block tile, BK=16, 256 thr, 8 warps of 64x32 (m16n8k8 frags).
// ---------------------------------------------------------------------------
__global__ __launch_bounds__(256) void gemm_tf32_kernel(
    const float* __restrict__ A, long long strideA, int lda,
    const float* __restrict__ B, long long strideB,
    float* __restrict__ C, long long strideC,
    int Kdim, const float* __restrict__ bias)
{
    const int NN = 4096;
    const int n0 = blockIdx.x * 128;
    const int m0 = blockIdx.y * 128;
    const long long bz = blockIdx.z;
    A += bz * strideA;  B += bz * strideB;  C += bz * strideC;

    __shared__ unsigned As[16][SA];   // [k][m ^ ((k>>2)<<3)]
    __shared__ unsigned Bs[16][SA];   // [k][n]

    const int tid  = threadIdx.x;
    const int lane = tid & 31, warp = tid >> 5;
    const int wm = warp >> 2, wn = warp & 3;     // 2 x 4 warp grid
    const int g  = lane >> 2, tig = lane & 3;

    const int arow = tid >> 2, ac = tid & 3;     // A: rows 0..63 (+64), k-chunk ac
    const int brow = tid >> 5, bn = (tid & 31) * 4;  // B: rows 0..7 (+8)

    float acc[4][4][4];
    #pragma unroll
    for (int i = 0; i < 4; i++)
        #pragma unroll
        for (int j = 0; j < 4; j++)
            #pragma unroll
            for (int k = 0; k < 4; k++) acc[i][j][k] = 0.f;

    const float* Ap = A + (long long)m0 * lda;
    float4 av[2], bv[2];
    #pragma unroll
    for (int i = 0; i < 2; i++) {
        av[i] = *(const float4*)(Ap + (long long)(arow + 64 * i) * lda + ac * 4);
        bv[i] = *(const float4*)(B + (long long)(brow + 8 * i) * NN + n0 + bn);
    }

    for (int k0 = 0; ; k0 += 16) {
        // stage current tile to smem (tf32-converted)
        #pragma unroll
        for (int i = 0; i < 2; i++) {
            const int r  = (arow + 64 * i) ^ (ac << 3);
            As[4 * ac + 0][r] = f2tf32(av[i].x);
            As[4 * ac + 1][r] = f2tf32(av[i].y);
            As[4 * ac + 2][r] = f2tf32(av[i].z);
            As[4 * ac + 3][r] = f2tf32(av[i].w);
            const int br = brow + 8 * i;
            Bs[br][bn + 0] = f2tf32(bv[i].x);
            Bs[br][bn + 1] = f2tf32(bv[i].y);
            Bs[br][bn + 2] = f2tf32(bv[i].z);
            Bs[br][bn + 3] = f2tf32(bv[i].w);
        }
        __syncthreads();

        const bool more = (k0 + 16 < Kdim);
        if (more) {
            const int k1 = k0 + 16;
            #pragma unroll
            for (int i = 0; i < 2; i++) {
                av[i] = *(const float4*)(Ap + (long long)(arow + 64 * i) * lda + k1 + ac * 4);
                bv[i] = *(const float4*)(B + (long long)(k1 + brow + 8 * i) * NN + n0 + bn);
            }
        }

        #pragma unroll
        for (int kk = 0; kk < 16; kk += 8) {
            unsigned a[4][4], bf[4][2];
            const int xr  = (kk >> 2) << 3;   // 0 or 16
            const int xr2 = xr + 8;           // 8 or 24
            #pragma unroll
            for (int mt = 0; mt < 4; mt++) {
                const int m = wm * 64 + mt * 16 + g;
                a[mt][0] = As[kk + tig    ][m       ^ xr ];
                a[mt][1] = As[kk + tig    ][(m + 8) ^ xr ];
                a[mt][2] = As[kk + tig + 4][m       ^ xr2];
                a[mt][3] = As[kk + tig + 4][(m + 8) ^ xr2];
            }
            #pragma unroll
            for (int nt = 0; nt < 4; nt++) {
                const int n = wn * 32 + nt * 8 + g;
                bf[nt][0] = Bs[kk + tig    ][n];
                bf[nt][1] = Bs[kk + tig + 4][n];
            }
            #pragma unroll
            for (int mt = 0; mt < 4; mt++)
                #pragma unroll
                for (int nt = 0; nt < 4; nt++)
                    mma8(acc[mt][nt], a[mt], bf[nt]);
        }

        if (!more) break;
        __syncthreads();
    }

    // epilogue
    #pragma unroll
    for (int mt = 0; mt < 4; mt++) {
        const int m = m0 + wm * 64 + mt * 16 + g;
        const float bb0 = bias ? bias[m]     : 0.f;
        const float bb1 = bias ? bias[m + 8] : 0.f;
        #pragma unroll
        for (int nt = 0; nt < 4; nt++) {
            const int n = n0 + wn * 32 + nt * 8 + 2 * tig;
            float2 v0 = make_float2(acc[mt][nt][0] + bb0, acc[mt][nt][1] + bb0);
            float2 v1 = make_float2(acc[mt][nt][2] + bb1, acc[mt][nt][3] + bb1);
            *(float2*)(C + (long long)m * NN + n)       = v0;
            *(float2*)(C + (long long)(m + 8) * NN + n) = v1;
        }
    }
}

// ---------------------------------------------------------------------------
// q softmax over d (64, strided), * SCALE. In place on qkv rows 0..255.
// ---------------------------------------------------------------------------
__global__ __launch_bounds__(256) void softmax_q_kernel(float* __restrict__ qkv)
{
    const int n = blockIdx.x * 256 + threadIdx.x;
    const int h = blockIdx.y;
    const int b = blockIdx.z;
    float* base = qkv + ((long long)b * 768 + h * 64) * 4096 + n;

    float v[64];
    float m = -1e30f;
    #pragma unroll
    for (int d = 0; d < 64; d++) {
        v[d] = base[(long long)d * 4096];
        m = fmaxf(m, v[d]);
    }
    float s = 0.f;
    #pragma unroll
    for (int d = 0; d < 64; d++) {
        v[d] = expf(v[d] - m);
        s += v[d];
    }
    const float r = 0.125f / s;
    #pragma unroll
    for (int d = 0; d < 64; d++)
        base[(long long)d * 4096] = v[d] * r;
}

// ---------------------------------------------------------------------------
// k softmax over n (4096, contiguous). One block per (b, row).
// ---------------------------------------------------------------------------
__global__ __launch_bounds__(256) void softmax_k_kernel(float* __restrict__ qkv)
{
    const int r   = blockIdx.x;
    const int b   = r >> 8;
    const int rem = r & 255;
    float* base = qkv + ((long long)b * 768 + 256 + rem) * 4096;
    const int tid = threadIdx.x;

    float v[16];
    float m = -1e30f;
    #pragma unroll
    for (int i = 0; i < 16; i++) {
        v[i] = base[tid + i * 256];
        m = fmaxf(m, v[i]);
    }
    __shared__ float red[8];
    #pragma unroll
    for (int o = 16; o; o >>= 1) m = fmaxf(m, __shfl_xor_sync(0xffffffffu, m, o));
    if ((tid & 31) == 0) red[tid >> 5] = m;
    __syncthreads();
    if (tid == 0) {
        float t = red[0];
        for (int i = 1; i < 8; i++) t = fmaxf(t, red[i]);
        red[0] = t;
    }
    __syncthreads();
    m = red[0];
    __syncthreads();

    float s = 0.f;
    #pragma unroll
    for (int i = 0; i < 16; i++) {
        v[i] = expf(v[i] - m);
        s += v[i];
    }
    #pragma unroll
    for (int o = 16; o; o >>= 1) s += __shfl_xor_sync(0xffffffffu, s, o);
    if ((tid & 31) == 0) red[tid >> 5] = s;
    __syncthreads();
    if (tid == 0) {
        float t = 0.f;
        for (int i = 0; i < 8; i++) t += red[i];
        red[0] = t;
    }
    __syncthreads();
    const float inv = 1.f / red[0];
    #pragma unroll
    for (int i = 0; i < 16; i++)
        base[tid + i * 256] = v[i] * inv;
}

// ---------------------------------------------------------------------------
// context[b,h,d,e] += sum_{n in split} k[b,h,d,n] * v[b,h,e,n]
// grid (4 heads, 16 batch, 16 splits); atomicAdd into zeroed ctx.
// ---------------------------------------------------------------------------
__global__ __launch_bounds__(256) void context_kernel(
    const float* __restrict__ qkv, float* __restrict__ ctx)
{
    const int h  = blockIdx.x;
    const int b  = blockIdx.y;
    const int sp = blockIdx.z;
    const float* Kp = qkv + ((long long)b * 768 + 256 + h * 64) * 4096;
    const float* Vp = qkv + ((long long)b * 768 + 512 + h * 64) * 4096;

    __shared__ float ks[64][33];
    __shared__ float vs[64][33];

    const int tid = threadIdx.x;
    const int ty = tid >> 4, tx = tid & 15;
    float acc[4][4];
    #pragma unroll
    for (int i = 0; i < 4; i++)
        #pragma unroll
        for (int j = 0; j < 4; j++) acc[i][j] = 0.f;

    const int nbeg = sp * 256;
    for (int n0 = nbeg; n0 < nbeg + 256; n0 += 32) {
        __syncthreads();
        #pragma unroll
        for (int i = 0; i < 8; i++) {
            const int idx = tid + i * 256;
            const int d = idx >> 5, j = idx & 31;
            ks[d][j] = Kp[(long long)d * 4096 + n0 + j];
            vs[d][j] = Vp[(long long)d * 4096 + n0 + j];
        }
        __syncthreads();
        #pragma unroll
        for (int j = 0; j < 32; j++) {
            float a[4], bb[4];
            #pragma unroll
            for (int i = 0; i < 4; i++) a[i]  = ks[ty * 4 + i][j];
            #pragma unroll
            for (int i = 0; i < 4; i++) bb[i] = vs[tx * 4 + i][j];
            #pragma unroll
            for (int i = 0; i < 4; i++)
                #pragma unroll
                for (int e = 0; e < 4; e++)
                    acc[i][e] = fmaf(a[i], bb[e], acc[i][e]);
        }
    }
    float* cbase = ctx + (long long)(b * 4 + h) * 64 * 64;
    #pragma unroll
    for (int i = 0; i < 4; i++)
        #pragma unroll
        for (int e = 0; e < 4; e++)
            atomicAdd(&cbase[(ty * 4 + i) * 64 + tx * 4 + e], acc[i][e]);
}

// ---------------------------------------------------------------------------
// W2[b][o, h*64+d] = sum_e w_out[o, h*64+e] * ctx[b,h,d,e]
// ---------------------------------------------------------------------------
__global__ __launch_bounds__(256) void w2_kernel(
    const float* __restrict__ ctx, const float* __restrict__ w_out,
    float* __restrict__ w2)
{
    const int h = blockIdx.x;
    const int b = blockIdx.y;
    __shared__ float cs[64][65];
    __shared__ float ws[64][65];
    const int tid = threadIdx.x;

    const float* cbase = ctx + (long long)(b * 4 + h) * 4096;
    #pragma unroll
    for (int i = 0; i < 16; i++) {
        const int idx = tid + i * 256;
        cs[idx >> 6][idx & 63] = cbase[idx];
    }
    float* w2base = w2 + (long long)b * 65536;

    for (int oc = 0; oc < 4; oc++) {
        __syncthreads();
        #pragma unroll
        for (int i = 0; i < 16; i++) {
            const int idx = tid + i * 256;
            const int ol = idx >> 6, e = idx & 63;
            ws[ol][e] = w_out[(oc * 64 + ol) * 256 + h * 64 + e];
        }
        __syncthreads();
        const int ol    = tid & 63;
        const int dbase = (tid >> 6) * 16;
        for (int dd = 0; dd < 16; dd++) {
            const int d = dbase + dd;
            float s = 0.f;
            #pragma unroll
            for (int e = 0; e < 64; e++)
                s = fmaf(ws[ol][e], cs[d][e], s);
            w2base[(oc * 64 + ol) * 256 + h * 64 + d] = s;
        }
    }
}

// ---------------------------------------------------------------------------
extern "C" void kernel_launch(void* const* d_in, const int* in_sizes, int n_in,
                              void* d_out, int out_size)
{
    const float *x = nullptr, *w_qkv = nullptr, *w_out = nullptr, *b_out = nullptr;
    for (int i = 0; i < n_in; i++) {
        switch (in_sizes[i]) {
            case 16 * 256 * 4096: x     = (const float*)d_in[i]; break;
            case 768 * 256:       w_qkv = (const float*)d_in[i]; break;
            case 256 * 256:       w_out = (const float*)d_in[i]; break;
            case 256:             b_out = (const float*)d_in[i]; break;
        }
    }
    float* out = (float*)d_out;

    float *qkv, *ctx, *w2;
    cudaGetSymbolAddress((void**)&qkv, g_qkv);
    cudaGetSymbolAddress((void**)&ctx, g_ctx);
    cudaGetSymbolAddress((void**)&w2,  g_w2);

    // 1) qkv[b] = w_qkv @ x[b]  (768x4096, K=256) x16  — tf32 tensor cores
    gemm_tf32_kernel<<<dim3(32, 6, 16), 256>>>(
        w_qkv, 0LL, 256, x, 256LL * 4096, qkv, 768LL * 4096, 256, nullptr);

    // 2) q softmax over d, * SCALE
    softmax_q_kernel<<<dim3(16, 4, 16), 256>>>(qkv);

    // 3) k softmax over n
    softmax_k_kernel<<<4096, 256>>>(qkv);

    // 4) context = k @ v^T, split-K 16-way with atomics
    cudaMemsetAsync(ctx, 0, 16 * 4 * 64 * 64 * sizeof(float));
    context_kernel<<<dim3(4, 16, 16), 256>>>(qkv, ctx);

    // 5) W2[b] = w_out-slice @ ctx^T fusion
    w2_kernel<<<dim3(4, 16), 256>>>(ctx, w_out, w2);

    // 6) out[b] = W2[b] @ q[b] + b_out  (256x4096, K=256) x16 — tf32
    gemm_tf32_kernel<<<dim3(32, 2, 16), 256>>>(
        w2, 256LL * 256, 256, qkv, 768LL * 4096, out, 256LL * 4096, 256, b_out);
}

// round 4
// speedup vs baseline: 2.4280x; 1.0423x over previous
#include <cuda_runtime.h>

// Shapes: x (16,256,4096), w_qkv (768,256), w_out (256,256), b_out (256)
__device__ float g_qkv[16LL * 768 * 4096];   // qkv intermediate (q softmaxed in epilogue, k in place)
__device__ float g_ctx[16 * 4 * 64 * 64];    // context per (b, h)
__device__ float g_w2[16 * 256 * 256];       // fused (w_out x ctx) per batch

__device__ __forceinline__ unsigned f2tf32(float f) {
    unsigned u; asm("cvt.rna.tf32.f32 %0, %1;" : "=r"(u) : "f"(f)); return u;
}

__device__ __forceinline__ void mma8(float* c, const unsigned* a, const unsigned* b) {
    asm volatile(
        "mma.sync.aligned.m16n8k8.row.col.f32.tf32.tf32.f32 "
        "{%0,%1,%2,%3},{%4,%5,%6,%7},{%8,%9},{%0,%1,%2,%3};"
        : "+f"(c[0]), "+f"(c[1]), "+f"(c[2]), "+f"(c[3])
        : "r"(a[0]), "r"(a[1]), "r"(a[2]), "r"(a[3]), "r"(b[0]), "r"(b[1]));
}

#define SA 136

// ---------------------------------------------------------------------------
// TF32 tensor-core GEMM: C[b] = A[b](M x K, lda) @ B[b](K x 4096) [+bias]
// 128x128 block tile, BK=16, double-buffered smem, 8 warps of 64x32.
// If m0 < q_rows: fused softmax over the warp's 64 M-rows (one head) * 0.125.
// ---------------------------------------------------------------------------
__global__ __launch_bounds__(256) void gemm_tf32_kernel(
    const float* __restrict__ A, long long strideA, int lda,
    const float* __restrict__ B, long long strideB,
    float* __restrict__ C, long long strideC,
    int Kdim, const float* __restrict__ bias, int q_rows)
{
    const int NN = 4096;
    const int n0 = blockIdx.x * 128;
    const int m0 = blockIdx.y * 128;
    const long long bz = blockIdx.z;
    A += bz * strideA;  B += bz * strideB;  C += bz * strideC;

    __shared__ unsigned As[2][16][SA];   // [buf][k][m ^ ((k>>2)<<3)]
    __shared__ unsigned Bs[2][16][SA];   // [buf][k][n]

    const int tid  = threadIdx.x;
    const int lane = tid & 31, warp = tid >> 5;
    const int wm = warp >> 2, wn = warp & 3;     // 2 x 4 warp grid
    const int g  = lane >> 2, tig = lane & 3;

    const int arow = tid >> 2, ac = tid & 3;
    const int brow = tid >> 5, bn = (tid & 31) * 4;

    float acc[4][4][4];
    #pragma unroll
    for (int i = 0; i < 4; i++)
        #pragma unroll
        for (int j = 0; j < 4; j++)
            #pragma unroll
            for (int k = 0; k < 4; k++) acc[i][j][k] = 0.f;

    const float* Ap = A + (long long)m0 * lda;
    float4 av[2], bv[2];
    #pragma unroll
    for (int i = 0; i < 2; i++) {
        av[i] = *(const float4*)(Ap + (long long)(arow + 64 * i) * lda + ac * 4);
        bv[i] = *(const float4*)(B + (long long)(brow + 8 * i) * NN + n0 + bn);
    }
    // stage tile 0 into buffer 0
    #pragma unroll
    for (int i = 0; i < 2; i++) {
        const int r = (arow + 64 * i) ^ (ac << 3);
        As[0][4 * ac + 0][r] = f2tf32(av[i].x);
        As[0][4 * ac + 1][r] = f2tf32(av[i].y);
        As[0][4 * ac + 2][r] = f2tf32(av[i].z);
        As[0][4 * ac + 3][r] = f2tf32(av[i].w);
        const int br = brow + 8 * i;
        Bs[0][br][bn + 0] = f2tf32(bv[i].x);
        Bs[0][br][bn + 1] = f2tf32(bv[i].y);
        Bs[0][br][bn + 2] = f2tf32(bv[i].z);
        Bs[0][br][bn + 3] = f2tf32(bv[i].w);
    }
    __syncthreads();

    for (int k0 = 0; ; k0 += 16) {
        const int cur = (k0 >> 4) & 1;
        const bool more = (k0 + 16 < Kdim);
        if (more) {
            const int k1 = k0 + 16;
            #pragma unroll
            for (int i = 0; i < 2; i++) {
                av[i] = *(const float4*)(Ap + (long long)(arow + 64 * i) * lda + k1 + ac * 4);
                bv[i] = *(const float4*)(B + (long long)(k1 + brow + 8 * i) * NN + n0 + bn);
            }
        }

        #pragma unroll
        for (int kk = 0; kk < 16; kk += 8) {
            unsigned a[4][4], bf[4][2];
            const int xr  = (kk >> 2) << 3;
            const int xr2 = xr + 8;
            #pragma unroll
            for (int mt = 0; mt < 4; mt++) {
                const int m = wm * 64 + mt * 16 + g;
                a[mt][0] = As[cur][kk + tig    ][m       ^ xr ];
                a[mt][1] = As[cur][kk + tig    ][(m + 8) ^ xr ];
                a[mt][2] = As[cur][kk + tig + 4][m       ^ xr2];
                a[mt][3] = As[cur][kk + tig + 4][(m + 8) ^ xr2];
            }
            #pragma unroll
            for (int nt = 0; nt < 4; nt++) {
                const int n = wn * 32 + nt * 8 + g;
                bf[nt][0] = Bs[cur][kk + tig    ][n];
                bf[nt][1] = Bs[cur][kk + tig + 4][n];
            }
            #pragma unroll
            for (int mt = 0; mt < 4; mt++)
                #pragma unroll
                for (int nt = 0; nt < 4; nt++)
                    mma8(acc[mt][nt], a[mt], bf[nt]);
        }

        if (!more) break;

        const int nxt = cur ^ 1;
        #pragma unroll
        for (int i = 0; i < 2; i++) {
            const int r = (arow + 64 * i) ^ (ac << 3);
            As[nxt][4 * ac + 0][r] = f2tf32(av[i].x);
            As[nxt][4 * ac + 1][r] = f2tf32(av[i].y);
            As[nxt][4 * ac + 2][r] = f2tf32(av[i].z);
            As[nxt][4 * ac + 3][r] = f2tf32(av[i].w);
            const int br = brow + 8 * i;
            Bs[nxt][br][bn + 0] = f2tf32(bv[i].x);
            Bs[nxt][br][bn + 1] = f2tf32(bv[i].y);
            Bs[nxt][br][bn + 2] = f2tf32(bv[i].z);
            Bs[nxt][br][bn + 3] = f2tf32(bv[i].w);
        }
        __syncthreads();
    }

    // fused q-softmax: warp's 64 M-rows are exactly one head; axis d == M dir.
    if (m0 < q_rows) {
        #pragma unroll
        for (int nt = 0; nt < 4; nt++)
            #pragma unroll
            for (int c = 0; c < 2; c++) {
                float mx = -1e30f;
                #pragma unroll
                for (int mt = 0; mt < 4; mt++) {
                    mx = fmaxf(mx, acc[mt][nt][c]);
                    mx = fmaxf(mx, acc[mt][nt][c + 2]);
                }
                mx = fmaxf(mx, __shfl_xor_sync(0xffffffffu, mx, 4));
                mx = fmaxf(mx, __shfl_xor_sync(0xffffffffu, mx, 8));
                mx = fmaxf(mx, __shfl_xor_sync(0xffffffffu, mx, 16));
                float s = 0.f;
                #pragma unroll
                for (int mt = 0; mt < 4; mt++) {
                    acc[mt][nt][c]     = expf(acc[mt][nt][c]     - mx);
                    acc[mt][nt][c + 2] = expf(acc[mt][nt][c + 2] - mx);
                    s += acc[mt][nt][c] + acc[mt][nt][c + 2];
                }
                s += __shfl_xor_sync(0xffffffffu, s, 4);
                s += __shfl_xor_sync(0xffffffffu, s, 8);
                s += __shfl_xor_sync(0xffffffffu, s, 16);
                const float r = 0.125f / s;   // SCALE = 64^-0.5
                #pragma unroll
                for (int mt = 0; mt < 4; mt++) {
                    acc[mt][nt][c]     *= r;
                    acc[mt][nt][c + 2] *= r;
                }
            }
    }

    #pragma unroll
    for (int mt = 0; mt < 4; mt++) {
        const int m = m0 + wm * 64 + mt * 16 + g;
        const float bb0 = bias ? bias[m]     : 0.f;
        const float bb1 = bias ? bias[m + 8] : 0.f;
        #pragma unroll
        for (int nt = 0; nt < 4; nt++) {
            const int n = n0 + wn * 32 + nt * 8 + 2 * tig;
            float2 v0 = make_float2(acc[mt][nt][0] + bb0, acc[mt][nt][1] + bb0);
            float2 v1 = make_float2(acc[mt][nt][2] + bb1, acc[mt][nt][3] + bb1);
            *(float2*)(C + (long long)m * NN + n)       = v0;
            *(float2*)(C + (long long)(m + 8) * NN + n) = v1;
        }
    }
}

// ---------------------------------------------------------------------------
// k softmax over n (4096, contiguous). One block per (b, row).
// ---------------------------------------------------------------------------
__global__ __launch_bounds__(256) void softmax_k_kernel(float* __restrict__ qkv)
{
    const int r   = blockIdx.x;
    const int b   = r >> 8;
    const int rem = r & 255;
    float* base = qkv + ((long long)b * 768 + 256 + rem) * 4096;
    const int tid = threadIdx.x;

    float v[16];
    float m = -1e30f;
    #pragma unroll
    for (int i = 0; i < 16; i++) {
        v[i] = base[tid + i * 256];
        m = fmaxf(m, v[i]);
    }
    __shared__ float red[8];
    #pragma unroll
    for (int o = 16; o; o >>= 1) m = fmaxf(m, __shfl_xor_sync(0xffffffffu, m, o));
    if ((tid & 31) == 0) red[tid >> 5] = m;
    __syncthreads();
    if (tid == 0) {
        float t = red[0];
        for (int i = 1; i < 8; i++) t = fmaxf(t, red[i]);
        red[0] = t;
    }
    __syncthreads();
    m = red[0];
    __syncthreads();

    float s = 0.f;
    #pragma unroll
    for (int i = 0; i < 16; i++) {
        v[i] = expf(v[i] - m);
        s += v[i];
    }
    #pragma unroll
    for (int o = 16; o; o >>= 1) s += __shfl_xor_sync(0xffffffffu, s, o);
    if ((tid & 31) == 0) red[tid >> 5] = s;
    __syncthreads();
    if (tid == 0) {
        float t = 0.f;
        for (int i = 0; i < 8; i++) t += red[i];
        red[0] = t;
    }
    __syncthreads();
    const float inv = 1.f / red[0];
    #pragma unroll
    for (int i = 0; i < 16; i++)
        base[tid + i * 256] = v[i] * inv;
}

// ---------------------------------------------------------------------------
// context[b,h,d,e] += sum_{n in split} k[b,h,d,n] * v[b,h,e,n]
// grid (4, 16, 16 splits); float4 loads, 64-wide n tiles; atomicAdd into ctx.
// ---------------------------------------------------------------------------
__global__ __launch_bounds__(256, 4) void context_kernel(
    const float* __restrict__ qkv, float* __restrict__ ctx)
{
    const int h  = blockIdx.x;
    const int b  = blockIdx.y;
    const int sp = blockIdx.z;
    const float* Kp = qkv + ((long long)b * 768 + 256 + h * 64) * 4096;
    const float* Vp = qkv + ((long long)b * 768 + 512 + h * 64) * 4096;

    __shared__ float ks[64][65];
    __shared__ float vs[64][65];

    const int tid = threadIdx.x;
    const int ty = tid >> 4, tx = tid & 15;
    const int lrow = tid >> 4;          // 0..15
    const int lc4  = (tid & 15) * 4;    // 0..60

    float acc[4][4];
    #pragma unroll
    for (int i = 0; i < 4; i++)
        #pragma unroll
        for (int j = 0; j < 4; j++) acc[i][j] = 0.f;

    const int nbeg = sp * 256;
    for (int n0 = nbeg; n0 < nbeg + 256; n0 += 64) {
        __syncthreads();
        #pragma unroll
        for (int i = 0; i < 4; i++) {
            const int row = lrow + i * 16;
            float4 kv = *(const float4*)(Kp + (long long)row * 4096 + n0 + lc4);
            float4 vv = *(const float4*)(Vp + (long long)row * 4096 + n0 + lc4);
            ks[row][lc4 + 0] = kv.x; ks[row][lc4 + 1] = kv.y;
            ks[row][lc4 + 2] = kv.z; ks[row][lc4 + 3] = kv.w;
            vs[row][lc4 + 0] = vv.x; vs[row][lc4 + 1] = vv.y;
            vs[row][lc4 + 2] = vv.z; vs[row][lc4 + 3] = vv.w;
        }
        __syncthreads();
        #pragma unroll 8
        for (int j = 0; j < 64; j++) {
            float a[4], bb[4];
            #pragma unroll
            for (int i = 0; i < 4; i++) a[i]  = ks[ty * 4 + i][j];
            #pragma unroll
            for (int i = 0; i < 4; i++) bb[i] = vs[tx * 4 + i][j];
            #pragma unroll
            for (int i = 0; i < 4; i++)
                #pragma unroll
                for (int e = 0; e < 4; e++)
                    acc[i][e] = fmaf(a[i], bb[e], acc[i][e]);
        }
    }
    float* cbase = ctx + (long long)(b * 4 + h) * 64 * 64;
    #pragma unroll
    for (int i = 0; i < 4; i++)
        #pragma unroll
        for (int e = 0; e < 4; e++)
            atomicAdd(&cbase[(ty * 4 + i) * 64 + tx * 4 + e], acc[i][e]);
}

// ---------------------------------------------------------------------------
// W2[b][o, h*64+d] = sum_e w_out[o, h*64+e] * ctx[b,h,d,e]
// ---------------------------------------------------------------------------
__global__ __launch_bounds__(256) void w2_kernel(
    const float* __restrict__ ctx, const float* __restrict__ w_out,
    float* __restrict__ w2)
{
    const int h = blockIdx.x;
    const int b = blockIdx.y;
    __shared__ float cs[64][65];
    __shared__ float ws[64][65];
    const int tid = threadIdx.x;

    const float* cbase = ctx + (long long)(b * 4 + h) * 4096;
    #pragma unroll
    for (int i = 0; i < 16; i++) {
        const int idx = tid + i * 256;
        cs[idx >> 6][idx & 63] = cbase[idx];
    }
    float* w2base = w2 + (long long)b * 65536;

    for (int oc = 0; oc < 4; oc++) {
        __syncthreads();
        #pragma unroll
        for (int i = 0; i < 16; i++) {
            const int idx = tid + i * 256;
            const int ol = idx >> 6, e = idx & 63;
            ws[ol][e] = w_out[(oc * 64 + ol) * 256 + h * 64 + e];
        }
        __syncthreads();
        const int ol    = tid & 63;
        const int dbase = (tid >> 6) * 16;
        for (int dd = 0; dd < 16; dd++) {
            const int d = dbase + dd;
            float s = 0.f;
            #pragma unroll
            for (int e = 0; e < 64; e++)
                s = fmaf(ws[ol][e], cs[d][e], s);
            w2base[(oc * 64 + ol) * 256 + h * 64 + d] = s;
        }
    }
}

// ---------------------------------------------------------------------------
extern "C" void kernel_launch(void* const* d_in, const int* in_sizes, int n_in,
                              void* d_out, int out_size)
{
    const float *x = nullptr, *w_qkv = nullptr, *w_out = nullptr, *b_out = nullptr;
    for (int i = 0; i < n_in; i++) {
        switch (in_sizes[i]) {
            case 16 * 256 * 4096: x     = (const float*)d_in[i]; break;
            case 768 * 256:       w_qkv = (const float*)d_in[i]; break;
            case 256 * 256:       w_out = (const float*)d_in[i]; break;
            case 256:             b_out = (const float*)d_in[i]; break;
        }
    }
    float* out = (float*)d_out;

    float *qkv, *ctx, *w2;
    cudaGetSymbolAddress((void**)&qkv, g_qkv);
    cudaGetSymbolAddress((void**)&ctx, g_ctx);
    cudaGetSymbolAddress((void**)&w2,  g_w2);

    // 1) qkv[b] = w_qkv @ x[b], q-softmax fused into epilogue for rows < 256
    gemm_tf32_kernel<<<dim3(32, 6, 16), 256>>>(
        w_qkv, 0LL, 256, x, 256LL * 4096, qkv, 768LL * 4096, 256, nullptr, 256);

    // 2) k softmax over n
    softmax_k_kernel<<<4096, 256>>>(qkv);

    // 3) context = k @ v^T, split-K 16-way with atomics
    cudaMemsetAsync(ctx, 0, 16 * 4 * 64 * 64 * sizeof(float));
    context_kernel<<<dim3(4, 16, 16), 256>>>(qkv, ctx);

    // 4) W2[b] = w_out-slice @ ctx^T fusion
    w2_kernel<<<dim3(4, 16), 256>>>(ctx, w_out, w2);

    // 5) out[b] = W2[b] @ q[b] + b_out
    gemm_tf32_kernel<<<dim3(32, 2, 16), 256>>>(
        w2, 256LL * 256, 256, qkv, 768LL * 4096, out, 256LL * 4096, 256, b_out, 0);
}

// round 5
// speedup vs baseline: 2.7567x; 1.1354x over previous
#include <cuda_runtime.h>

// Shapes: x (16,256,4096), w_qkv (768,256), w_out (256,256), b_out (256)
__device__ float  g_qkv[16LL * 768 * 4096];  // qkv (q softmaxed in epilogue; k RAW)
__device__ float  g_ctx[16 * 4 * 64 * 64];   // context per (b, h)
__device__ float  g_w2[16 * 256 * 256];      // fused (w_out x ctx) per batch
__device__ float2 g_kstats[16 * 256];        // per k-row: (max, 1/sum)

__device__ __forceinline__ unsigned f2tf32(float f) {
    unsigned u; asm("cvt.rna.tf32.f32 %0, %1;" : "=r"(u) : "f"(f)); return u;
}

__device__ __forceinline__ void mma8(float* c, const unsigned* a, const unsigned* b) {
    asm volatile(
        "mma.sync.aligned.m16n8k8.row.col.f32.tf32.tf32.f32 "
        "{%0,%1,%2,%3},{%4,%5,%6,%7},{%8,%9},{%0,%1,%2,%3};"
        : "+f"(c[0]), "+f"(c[1]), "+f"(c[2]), "+f"(c[3])
        : "r"(a[0]), "r"(a[1]), "r"(a[2]), "r"(a[3]), "r"(b[0]), "r"(b[1]));
}

#define SA 136

// ---------------------------------------------------------------------------
// TF32 tensor-core GEMM: C[b] = A[b](M x K, lda) @ B[b](K x 4096) [+bias]
// 128x128 block tile, BK=16, double-buffered smem, 8 warps of 64x32.
// If m0 < q_rows: fused softmax over the warp's 64 M-rows (one head) * 0.125.
// ---------------------------------------------------------------------------
__global__ __launch_bounds__(256) void gemm_tf32_kernel(
    const float* __restrict__ A, long long strideA, int lda,
    const float* __restrict__ B, long long strideB,
    float* __restrict__ C, long long strideC,
    int Kdim, const float* __restrict__ bias, int q_rows)
{
    const int NN = 4096;
    const int n0 = blockIdx.x * 128;
    const int m0 = blockIdx.y * 128;
    const long long bz = blockIdx.z;
    A += bz * strideA;  B += bz * strideB;  C += bz * strideC;

    __shared__ unsigned As[2][16][SA];
    __shared__ unsigned Bs[2][16][SA];

    const int tid  = threadIdx.x;
    const int lane = tid & 31, warp = tid >> 5;
    const int wm = warp >> 2, wn = warp & 3;
    const int g  = lane >> 2, tig = lane & 3;

    const int arow = tid >> 2, ac = tid & 3;
    const int brow = tid >> 5, bn = (tid & 31) * 4;

    float acc[4][4][4];
    #pragma unroll
    for (int i = 0; i < 4; i++)
        #pragma unroll
        for (int j = 0; j < 4; j++)
            #pragma unroll
            for (int k = 0; k < 4; k++) acc[i][j][k] = 0.f;

    const float* Ap = A + (long long)m0 * lda;
    float4 av[2], bv[2];
    #pragma unroll
    for (int i = 0; i < 2; i++) {
        av[i] = *(const float4*)(Ap + (long long)(arow + 64 * i) * lda + ac * 4);
        bv[i] = *(const float4*)(B + (long long)(brow + 8 * i) * NN + n0 + bn);
    }
    #pragma unroll
    for (int i = 0; i < 2; i++) {
        const int r = (arow + 64 * i) ^ (ac << 3);
        As[0][4 * ac + 0][r] = f2tf32(av[i].x);
        As[0][4 * ac + 1][r] = f2tf32(av[i].y);
        As[0][4 * ac + 2][r] = f2tf32(av[i].z);
        As[0][4 * ac + 3][r] = f2tf32(av[i].w);
        const int br = brow + 8 * i;
        Bs[0][br][bn + 0] = f2tf32(bv[i].x);
        Bs[0][br][bn + 1] = f2tf32(bv[i].y);
        Bs[0][br][bn + 2] = f2tf32(bv[i].z);
        Bs[0][br][bn + 3] = f2tf32(bv[i].w);
    }
    __syncthreads();

    for (int k0 = 0; ; k0 += 16) {
        const int cur = (k0 >> 4) & 1;
        const bool more = (k0 + 16 < Kdim);
        if (more) {
            const int k1 = k0 + 16;
            #pragma unroll
            for (int i = 0; i < 2; i++) {
                av[i] = *(const float4*)(Ap + (long long)(arow + 64 * i) * lda + k1 + ac * 4);
                bv[i] = *(const float4*)(B + (long long)(k1 + brow + 8 * i) * NN + n0 + bn);
            }
        }

        #pragma unroll
        for (int kk = 0; kk < 16; kk += 8) {
            unsigned a[4][4], bf[4][2];
            const int xr  = (kk >> 2) << 3;
            const int xr2 = xr + 8;
            #pragma unroll
            for (int mt = 0; mt < 4; mt++) {
                const int m = wm * 64 + mt * 16 + g;
                a[mt][0] = As[cur][kk + tig    ][m       ^ xr ];
                a[mt][1] = As[cur][kk + tig    ][(m + 8) ^ xr ];
                a[mt][2] = As[cur][kk + tig + 4][m       ^ xr2];
                a[mt][3] = As[cur][kk + tig + 4][(m + 8) ^ xr2];
            }
            #pragma unroll
            for (int nt = 0; nt < 4; nt++) {
                const int n = wn * 32 + nt * 8 + g;
                bf[nt][0] = Bs[cur][kk + tig    ][n];
                bf[nt][1] = Bs[cur][kk + tig + 4][n];
            }
            #pragma unroll
            for (int mt = 0; mt < 4; mt++)
                #pragma unroll
                for (int nt = 0; nt < 4; nt++)
                    mma8(acc[mt][nt], a[mt], bf[nt]);
        }

        if (!more) break;

        const int nxt = cur ^ 1;
        #pragma unroll
        for (int i = 0; i < 2; i++) {
            const int r = (arow + 64 * i) ^ (ac << 3);
            As[nxt][4 * ac + 0][r] = f2tf32(av[i].x);
            As[nxt][4 * ac + 1][r] = f2tf32(av[i].y);
            As[nxt][4 * ac + 2][r] = f2tf32(av[i].z);
            As[nxt][4 * ac + 3][r] = f2tf32(av[i].w);
            const int br = brow + 8 * i;
            Bs[nxt][br][bn + 0] = f2tf32(bv[i].x);
            Bs[nxt][br][bn + 1] = f2tf32(bv[i].y);
            Bs[nxt][br][bn + 2] = f2tf32(bv[i].z);
            Bs[nxt][br][bn + 3] = f2tf32(bv[i].w);
        }
        __syncthreads();
    }

    if (m0 < q_rows) {
        #pragma unroll
        for (int nt = 0; nt < 4; nt++)
            #pragma unroll
            for (int c = 0; c < 2; c++) {
                float mx = -1e30f;
                #pragma unroll
                for (int mt = 0; mt < 4; mt++) {
                    mx = fmaxf(mx, acc[mt][nt][c]);
                    mx = fmaxf(mx, acc[mt][nt][c + 2]);
                }
                mx = fmaxf(mx, __shfl_xor_sync(0xffffffffu, mx, 4));
                mx = fmaxf(mx, __shfl_xor_sync(0xffffffffu, mx, 8));
                mx = fmaxf(mx, __shfl_xor_sync(0xffffffffu, mx, 16));
                float s = 0.f;
                #pragma unroll
                for (int mt = 0; mt < 4; mt++) {
                    acc[mt][nt][c]     = expf(acc[mt][nt][c]     - mx);
                    acc[mt][nt][c + 2] = expf(acc[mt][nt][c + 2] - mx);
                    s += acc[mt][nt][c] + acc[mt][nt][c + 2];
                }
                s += __shfl_xor_sync(0xffffffffu, s, 4);
                s += __shfl_xor_sync(0xffffffffu, s, 8);
                s += __shfl_xor_sync(0xffffffffu, s, 16);
                const float r = 0.125f / s;
                #pragma unroll
                for (int mt = 0; mt < 4; mt++) {
                    acc[mt][nt][c]     *= r;
                    acc[mt][nt][c + 2] *= r;
                }
            }
    }

    #pragma unroll
    for (int mt = 0; mt < 4; mt++) {
        const int m = m0 + wm * 64 + mt * 16 + g;
        const float bb0 = bias ? bias[m]     : 0.f;
        const float bb1 = bias ? bias[m + 8] : 0.f;
        #pragma unroll
        for (int nt = 0; nt < 4; nt++) {
            const int n = n0 + wn * 32 + nt * 8 + 2 * tig;
            float2 v0 = make_float2(acc[mt][nt][0] + bb0, acc[mt][nt][1] + bb0);
            float2 v1 = make_float2(acc[mt][nt][2] + bb1, acc[mt][nt][3] + bb1);
            *(float2*)(C + (long long)m * NN + n)       = v0;
            *(float2*)(C + (long long)(m + 8) * NN + n) = v1;
        }
    }
}

// ---------------------------------------------------------------------------
// k row stats: per k-row (max, 1/sum(exp(x-max))). k stays RAW in memory.
// ---------------------------------------------------------------------------
__global__ __launch_bounds__(256) void kstats_kernel(
    const float* __restrict__ qkv, float2* __restrict__ stats)
{
    const int r   = blockIdx.x;       // 0..4095 = b*256 + row
    const int b   = r >> 8;
    const int rem = r & 255;
    const float* base = qkv + ((long long)b * 768 + 256 + rem) * 4096;
    const int tid = threadIdx.x;

    float v[16];
    float m = -1e30f;
    #pragma unroll
    for (int i = 0; i < 16; i++) {
        v[i] = base[tid + i * 256];
        m = fmaxf(m, v[i]);
    }
    __shared__ float red[8];
    #pragma unroll
    for (int o = 16; o; o >>= 1) m = fmaxf(m, __shfl_xor_sync(0xffffffffu, m, o));
    if ((tid & 31) == 0) red[tid >> 5] = m;
    __syncthreads();
    if (tid == 0) {
        float t = red[0];
        for (int i = 1; i < 8; i++) t = fmaxf(t, red[i]);
        red[0] = t;
    }
    __syncthreads();
    m = red[0];
    __syncthreads();

    float s = 0.f;
    #pragma unroll
    for (int i = 0; i < 16; i++) s += expf(v[i] - m);
    #pragma unroll
    for (int o = 16; o; o >>= 1) s += __shfl_xor_sync(0xffffffffu, s, o);
    if ((tid & 31) == 0) red[tid >> 5] = s;
    __syncthreads();
    if (tid == 0) {
        float t = 0.f;
        for (int i = 0; i < 8; i++) t += red[i];
        stats[r] = make_float2(m, 1.f / t);
    }
}

// ---------------------------------------------------------------------------
// context[b,h,d,e] += (1/s_d) * sum_{n in split} exp(k[d,n]-m_d) * v[e,n]
// grid (4, 16, 16 splits); softmax normalization fused inline.
// ---------------------------------------------------------------------------
__global__ __launch_bounds__(256, 4) void context_kernel(
    const float* __restrict__ qkv, const float2* __restrict__ stats,
    float* __restrict__ ctx)
{
    const int h  = blockIdx.x;
    const int b  = blockIdx.y;
    const int sp = blockIdx.z;
    const float* Kp = qkv + ((long long)b * 768 + 256 + h * 64) * 4096;
    const float* Vp = qkv + ((long long)b * 768 + 512 + h * 64) * 4096;

    __shared__ float ks[64][65];
    __shared__ float vs[64][65];
    __shared__ float sm_m[64], sm_is[64];

    const int tid = threadIdx.x;
    if (tid < 64) {
        float2 st = stats[b * 256 + h * 64 + tid];
        sm_m[tid]  = st.x;
        sm_is[tid] = st.y;
    }
    __syncthreads();

    const int ty = tid >> 4, tx = tid & 15;
    const int lrow = tid >> 4;
    const int lc4  = (tid & 15) * 4;

    float acc[4][4];
    #pragma unroll
    for (int i = 0; i < 4; i++)
        #pragma unroll
        for (int j = 0; j < 4; j++) acc[i][j] = 0.f;

    const int nbeg = sp * 256;
    for (int n0 = nbeg; n0 < nbeg + 256; n0 += 64) {
        __syncthreads();
        #pragma unroll
        for (int i = 0; i < 4; i++) {
            const int row = lrow + i * 16;
            const float mr = sm_m[row];
            float4 kv = *(const float4*)(Kp + (long long)row * 4096 + n0 + lc4);
            float4 vv = *(const float4*)(Vp + (long long)row * 4096 + n0 + lc4);
            ks[row][lc4 + 0] = expf(kv.x - mr);
            ks[row][lc4 + 1] = expf(kv.y - mr);
            ks[row][lc4 + 2] = expf(kv.z - mr);
            ks[row][lc4 + 3] = expf(kv.w - mr);
            vs[row][lc4 + 0] = vv.x; vs[row][lc4 + 1] = vv.y;
            vs[row][lc4 + 2] = vv.z; vs[row][lc4 + 3] = vv.w;
        }
        __syncthreads();
        #pragma unroll 8
        for (int j = 0; j < 64; j++) {
            float a[4], bb[4];
            #pragma unroll
            for (int i = 0; i < 4; i++) a[i]  = ks[ty * 4 + i][j];
            #pragma unroll
            for (int i = 0; i < 4; i++) bb[i] = vs[tx * 4 + i][j];
            #pragma unroll
            for (int i = 0; i < 4; i++)
                #pragma unroll
                for (int e = 0; e < 4; e++)
                    acc[i][e] = fmaf(a[i], bb[e], acc[i][e]);
        }
    }
    float* cbase = ctx + (long long)(b * 4 + h) * 64 * 64;
    #pragma unroll
    for (int i = 0; i < 4; i++) {
        const float is = sm_is[ty * 4 + i];
        #pragma unroll
        for (int e = 0; e < 4; e++)
            atomicAdd(&cbase[(ty * 4 + i) * 64 + tx * 4 + e], acc[i][e] * is);
    }
}

// ---------------------------------------------------------------------------
// W2[b][o, h*64+d] = sum_e w_out[o, h*64+e] * ctx[b,h,d,e]
// grid (2 oc, 4 h, 16 b); transposed smem; 8x4 register tile per thread.
// ---------------------------------------------------------------------------
__global__ __launch_bounds__(256) void w2_kernel(
    const float* __restrict__ ctx, const float* __restrict__ w_out,
    float* __restrict__ w2)
{
    const int oc = blockIdx.x;   // 0..1 (128 o-rows each)
    const int h  = blockIdx.y;
    const int b  = blockIdx.z;

    __shared__ float wt[64][128];  // [e][o]  (32 KB)
    __shared__ float ct[64][64];   // [e][d]  (16 KB)

    const int tid = threadIdx.x;

    // load w_out chunk transposed: o = tid/2 (0..127), e span 32 per half
    {
        const int o = tid >> 1;
        const int eb = (tid & 1) * 32;
        const float* wrow = w_out + (long long)(oc * 128 + o) * 256 + h * 64 + eb;
        #pragma unroll
        for (int j = 0; j < 8; j++) {
            float4 v = *(const float4*)(wrow + j * 4);
            wt[eb + j * 4 + 0][o] = v.x;
            wt[eb + j * 4 + 1][o] = v.y;
            wt[eb + j * 4 + 2][o] = v.z;
            wt[eb + j * 4 + 3][o] = v.w;
        }
    }
    // load ctx transposed: d = tid/4 (0..63), e span 16
    {
        const int d  = tid >> 2;
        const int eb = (tid & 3) * 16;
        const float* crow = ctx + (long long)(b * 4 + h) * 4096 + d * 64 + eb;
        #pragma unroll
        for (int j = 0; j < 4; j++) {
            float4 v = *(const float4*)(crow + j * 4);
            ct[eb + j * 4 + 0][d] = v.x;
            ct[eb + j * 4 + 1][d] = v.y;
            ct[eb + j * 4 + 2][d] = v.z;
            ct[eb + j * 4 + 3][d] = v.w;
        }
    }
    __syncthreads();

    const int ty = tid >> 4, tx = tid & 15;   // o-tile 8, d-tile 4
    float acc[8][4];
    #pragma unroll
    for (int i = 0; i < 8; i++)
        #pragma unroll
        for (int j = 0; j < 4; j++) acc[i][j] = 0.f;

    #pragma unroll 4
    for (int e = 0; e < 64; e++) {
        float4 w0 = *(const float4*)&wt[e][ty * 8];
        float4 w1 = *(const float4*)&wt[e][ty * 8 + 4];
        float4 c0 = *(const float4*)&ct[e][tx * 4];
        const float wv[8] = {w0.x, w0.y, w0.z, w0.w, w1.x, w1.y, w1.z, w1.w};
        const float cv[4] = {c0.x, c0.y, c0.z, c0.w};
        #pragma unroll
        for (int i = 0; i < 8; i++)
            #pragma unroll
            for (int j = 0; j < 4; j++)
                acc[i][j] = fmaf(wv[i], cv[j], acc[i][j]);
    }

    float* w2base = w2 + (long long)b * 65536 + h * 64 + tx * 4;
    #pragma unroll
    for (int i = 0; i < 8; i++) {
        const int o = oc * 128 + ty * 8 + i;
        *(float4*)(w2base + (long long)o * 256) =
            make_float4(acc[i][0], acc[i][1], acc[i][2], acc[i][3]);
    }
}

// ---------------------------------------------------------------------------
extern "C" void kernel_launch(void* const* d_in, const int* in_sizes, int n_in,
                              void* d_out, int out_size)
{
    const float *x = nullptr, *w_qkv = nullptr, *w_out = nullptr, *b_out = nullptr;
    for (int i = 0; i < n_in; i++) {
        switch (in_sizes[i]) {
            case 16 * 256 * 4096: x     = (const float*)d_in[i]; break;
            case 768 * 256:       w_qkv = (const float*)d_in[i]; break;
            case 256 * 256:       w_out = (const float*)d_in[i]; break;
            case 256:             b_out = (const float*)d_in[i]; break;
        }
    }
    float* out = (float*)d_out;

    float *qkv, *ctx, *w2;
    float2* kstats;
    cudaGetSymbolAddress((void**)&qkv, g_qkv);
    cudaGetSymbolAddress((void**)&ctx, g_ctx);
    cudaGetSymbolAddress((void**)&w2,  g_w2);
    cudaGetSymbolAddress((void**)&kstats, g_kstats);

    // 1) qkv[b] = w_qkv @ x[b]; q-softmax fused into epilogue for rows < 256
    gemm_tf32_kernel<<<dim3(32, 6, 16), 256>>>(
        w_qkv, 0LL, 256, x, 256LL * 4096, qkv, 768LL * 4096, 256, nullptr, 256);

    // 2) k row stats only (no materialized softmax)
    kstats_kernel<<<4096, 256>>>(qkv, kstats);

    // 3) context = softmax_k @ v^T with inline normalization, split-K 16-way
    cudaMemsetAsync(ctx, 0, 16 * 4 * 64 * 64 * sizeof(float));
    context_kernel<<<dim3(4, 16, 16), 256>>>(qkv, kstats, ctx);

    // 4) W2[b] = w_out-slice @ ctx^T fusion
    w2_kernel<<<dim3(2, 4, 16), 256>>>(ctx, w_out, w2);

    // 5) out[b] = W2[b] @ q[b] + b_out
    gemm_tf32_kernel<<<dim3(32, 2, 16), 256>>>(
        w2, 256LL * 256, 256, qkv, 768LL * 4096, out, 256LL * 4096, 256, b_out, 0);
}